// round 1
// baseline (speedup 1.0000x reference)
#include <cuda_runtime.h>
#include <cuda_bf16.h>
#include <math.h>

// Problem constants
#define BB     4
#define CIN    256
#define HS     64           // source H=W
#define SFULL  512          // upsampled S
#define CC     8            // classes
#define SM     128          // after 4x4 pool
#define KP     4            // pool window
#define PP     8            // patch
#define LH     16           // SM/PP
#define LL     256          // LH*LH  (== K of matmul)
#define QQ     4096         // (SFULL/PP)^2
#define PSQ    64           // PP*PP (== N of matmul)

#define OUT_ELEMS  (BB*CC*SFULL*SFULL)          // 8388608
#define ATTN_ELEMS (BB*CC*QQ*LL)                // 8388608

// -------- scratch (device globals; no allocation allowed) --------
__device__ float g_y64[BB*CC*HS*HS];            // 1x1 conv output  [b][c][64][64]
__device__ float g_U[BB*CC*LL*PSQ];             // unfold, k-major  [bc][k=256][p=64]
__device__ float g_scale[BB*CC*QQ];             // 1/(nz+1e-5) per attention row
__device__ float g_corr[(size_t)BB*CC*QQ*PSQ];  // matmul result    [bc][q][p]  (33.5MB)

// ================= Kernel A: 1x1 conv (256 -> 8) =================
__global__ void conv1x1_kernel(const float* __restrict__ x,
                               const float* __restrict__ w,
                               const float* __restrict__ b) {
    __shared__ float ws[CC*CIN];
    __shared__ float bs[CC];
    for (int i = threadIdx.x; i < CC*CIN; i += blockDim.x) ws[i] = w[i];
    if (threadIdx.x < CC) bs[threadIdx.x] = b[threadIdx.x];
    __syncthreads();

    int pid = blockIdx.x * blockDim.x + threadIdx.x;   // 0 .. 4*4096
    if (pid >= BB*HS*HS) return;
    int bb = pid >> 12;
    int p  = pid & 4095;

    float acc[CC];
#pragma unroll
    for (int c = 0; c < CC; ++c) acc[c] = bs[c];

    const float* xp = x + (size_t)bb*CIN*HS*HS + p;
#pragma unroll 4
    for (int ic = 0; ic < CIN; ++ic) {
        float xv = xp[(size_t)ic*HS*HS];
#pragma unroll
        for (int c = 0; c < CC; ++c) acc[c] += xv * ws[c*CIN + ic];
    }
#pragma unroll
    for (int c = 0; c < CC; ++c)
        g_y64[(bb*CC + c)*HS*HS + p] = acc[c];
}

// ========= Kernel B: bilinear->argmax->4x4 pool -> unfold =========
// One thread per (b, u, v) output cell of fm [B][128][128]; writes directly
// into U with torch-Unfold ordering (k-major for the matmul).
__global__ void argmax_pool_kernel() {
    int idx = blockIdx.x * blockDim.x + threadIdx.x;
    if (idx >= BB*SM*SM) return;
    int bb = idx >> 14;
    int r  = idx & 16383;
    int u  = r >> 7;
    int v  = r & 127;

    const double sc = 63.0 / 511.0;
    int cnt[CC];
#pragma unroll
    for (int c = 0; c < CC; ++c) cnt[c] = 0;

    const float* yb = g_y64 + bb*CC*HS*HS;

#pragma unroll
    for (int i = 0; i < KP; ++i) {
        int s = u*KP + i;
        float ps = (float)(s * sc);
        int lo_s = (int)ps; if (lo_s > 63) lo_s = 63;
        float wsv = ps - (float)lo_s;
        int hi_s = lo_s + 1; if (hi_s > 63) hi_s = 63;
#pragma unroll
        for (int j = 0; j < KP; ++j) {
            int t = v*KP + j;
            float pt = (float)(t * sc);
            int lo_t = (int)pt; if (lo_t > 63) lo_t = 63;
            float wtv = pt - (float)lo_t;
            int hi_t = lo_t + 1; if (hi_t > 63) hi_t = 63;

            float w00 = (1.f-wsv)*(1.f-wtv);
            float w01 = (1.f-wsv)*wtv;
            float w10 = wsv*(1.f-wtv);
            float w11 = wsv*wtv;

            float best = -3.4e38f;
            int bi = 0;
#pragma unroll
            for (int c = 0; c < CC; ++c) {
                const float* yc = yb + c*HS*HS;
                float yv = w00*yc[lo_s*HS + lo_t] + w01*yc[lo_s*HS + hi_t]
                         + w10*yc[hi_s*HS + lo_t] + w11*yc[hi_s*HS + hi_t];
                if (yv > best) { best = yv; bi = c; }   // strict > : first max, matches jnp.argmax
            }
            cnt[bi]++;
        }
    }

    int p = ((u & 7) << 3) | (v & 7);          // pi*8 + pj
    int l = ((u >> 3) << 4) | (v >> 3);        // li*16 + lj
#pragma unroll
    for (int c = 0; c < CC; ++c)
        g_U[((bb*CC + c)*LL + l)*PSQ + p] = (float)cnt[c] * (1.f/16.f);
}

// ============ Kernel C: nz counts -> row scales ============
__global__ void nz_kernel(const float* __restrict__ attn) {
    int gtid = blockIdx.x * blockDim.x + threadIdx.x;
    int row  = gtid >> 5;
    int lane = gtid & 31;
    if (row >= BB*CC*QQ) return;
    const float* rp = attn + (size_t)row * LL;
    int cnt = 0;
#pragma unroll
    for (int k = lane; k < LL; k += 32)
        cnt += (rp[k] != 0.f);
#pragma unroll
    for (int o = 16; o; o >>= 1)
        cnt += __shfl_xor_sync(0xFFFFFFFFu, cnt, o);
    if (lane == 0)
        g_scale[row] = 1.f / ((float)cnt + 1e-5f);
}

// ============ Kernel D: batched GEMM (A/nz) @ U^T ============
// Per (b,c): C[4096,64] = A[4096,256] @ U[256,64], then row-scale.
// Block: 256 q-rows x 64 p, 512 threads, thread tile 4q x 8p.
#define KT 32
#define ASM_LD 33
#define SMEM_FLOATS (LL*PSQ + 256*ASM_LD)      // 16384 + 8448
__global__ void __launch_bounds__(512)
matmul_kernel(const float* __restrict__ attn) {
    extern __shared__ float smf[];
    float* Usm = smf;                 // [256][64]
    float* Asm = smf + LL*PSQ;        // [256][33]

    int bc = blockIdx.y;              // 0..31
    int q0 = blockIdx.x * 256;        // 0..15 tiles

    const float* A  = attn + (size_t)bc*QQ*LL;
    const float* Ug = g_U  + (size_t)bc*LL*PSQ;

    // load full U into smem (float4, fully coalesced)
    for (int i = threadIdx.x; i < (LL*PSQ)/4; i += 512)
        ((float4*)Usm)[i] = ((const float4*)Ug)[i];

    float acc[4][8];
#pragma unroll
    for (int i = 0; i < 4; ++i)
#pragma unroll
        for (int j = 0; j < 8; ++j) acc[i][j] = 0.f;

    int tx = threadIdx.x & 7;         // p block: p = tx*8 .. tx*8+7
    int ty = threadIdx.x >> 3;        // 0..63
    int qb = ty * 4;                  // local q base

    for (int kc = 0; kc < LL; kc += KT) {
        __syncthreads();              // U-load done (iter 0) / prior reads done
        // stage A chunk: 256 rows x 32 k
#pragma unroll
        for (int it = 0; it < 4; ++it) {
            int idx = threadIdx.x + it*512;     // 0..2047
            int qq = idx >> 3;
            int k4 = idx & 7;
            float4 val = *(const float4*)(A + (size_t)(q0+qq)*LL + kc + k4*4);
            float* dst = Asm + qq*ASM_LD + k4*4;
            dst[0] = val.x; dst[1] = val.y; dst[2] = val.z; dst[3] = val.w;
        }
        __syncthreads();

#pragma unroll
        for (int k = 0; k < KT; ++k) {
            const float* ur = Usm + (kc + k)*PSQ + tx*8;
            float4 u0 = *(const float4*)(ur);
            float4 u1 = *(const float4*)(ur + 4);
            float a0 = Asm[(qb+0)*ASM_LD + k];
            float a1 = Asm[(qb+1)*ASM_LD + k];
            float a2 = Asm[(qb+2)*ASM_LD + k];
            float a3 = Asm[(qb+3)*ASM_LD + k];
            acc[0][0] += a0*u0.x; acc[0][1] += a0*u0.y; acc[0][2] += a0*u0.z; acc[0][3] += a0*u0.w;
            acc[0][4] += a0*u1.x; acc[0][5] += a0*u1.y; acc[0][6] += a0*u1.z; acc[0][7] += a0*u1.w;
            acc[1][0] += a1*u0.x; acc[1][1] += a1*u0.y; acc[1][2] += a1*u0.z; acc[1][3] += a1*u0.w;
            acc[1][4] += a1*u1.x; acc[1][5] += a1*u1.y; acc[1][6] += a1*u1.z; acc[1][7] += a1*u1.w;
            acc[2][0] += a2*u0.x; acc[2][1] += a2*u0.y; acc[2][2] += a2*u0.z; acc[2][3] += a2*u0.w;
            acc[2][4] += a2*u1.x; acc[2][5] += a2*u1.y; acc[2][6] += a2*u1.z; acc[2][7] += a2*u1.w;
            acc[3][0] += a3*u0.x; acc[3][1] += a3*u0.y; acc[3][2] += a3*u0.z; acc[3][3] += a3*u0.w;
            acc[3][4] += a3*u1.x; acc[3][5] += a3*u1.y; acc[3][6] += a3*u1.z; acc[3][7] += a3*u1.w;
        }
    }

#pragma unroll
    for (int i = 0; i < 4; ++i) {
        int q = q0 + qb + i;
        float s = g_scale[bc*QQ + q];
        float* cp = g_corr + ((size_t)bc*QQ + q)*PSQ + tx*8;
#pragma unroll
        for (int j = 0; j < 8; ++j) cp[j] = acc[i][j] * s;
    }
}

// ============ Kernel E: fold + (corr+1)*y + log_softmax ============
__global__ void finalize_kernel(float* __restrict__ out) {
    int idx = blockIdx.x * blockDim.x + threadIdx.x;
    if (idx >= BB*SFULL*SFULL) return;
    int bb = idx >> 18;
    int r  = idx & 262143;
    int s  = r >> 9;
    int t  = r & 511;

    const double sc = 63.0 / 511.0;
    float ps = (float)(s * sc);
    int lo_s = (int)ps; if (lo_s > 63) lo_s = 63;
    float wsv = ps - (float)lo_s;
    int hi_s = lo_s + 1; if (hi_s > 63) hi_s = 63;

    float pt = (float)(t * sc);
    int lo_t = (int)pt; if (lo_t > 63) lo_t = 63;
    float wtv = pt - (float)lo_t;
    int hi_t = lo_t + 1; if (hi_t > 63) hi_t = 63;

    float w00 = (1.f-wsv)*(1.f-wtv);
    float w01 = (1.f-wsv)*wtv;
    float w10 = wsv*(1.f-wtv);
    float w11 = wsv*wtv;

    int q = ((s >> 3) << 6) | (t >> 3);
    int p = ((s & 7) << 3) | (t & 7);

    const float* yb = g_y64 + bb*CC*HS*HS;
    float v[CC];
    float m = -3.4e38f;
#pragma unroll
    for (int c = 0; c < CC; ++c) {
        const float* yc = yb + c*HS*HS;
        float yv = w00*yc[lo_s*HS + lo_t] + w01*yc[lo_s*HS + hi_t]
                 + w10*yc[hi_s*HS + lo_t] + w11*yc[hi_s*HS + hi_t];
        float cr = g_corr[((size_t)(bb*CC + c)*QQ + q)*PSQ + p];
        v[c] = (cr + 1.f) * yv;
        m = fmaxf(m, v[c]);
    }
    float sum = 0.f;
#pragma unroll
    for (int c = 0; c < CC; ++c) sum += __expf(v[c] - m);
    float lse = logf(sum) + m;
#pragma unroll
    for (int c = 0; c < CC; ++c)
        out[(((size_t)(bb*CC + c)) << 18) + (s << 9) + t] = v[c] - lse;
}

// ======================= launch =======================
extern "C" void kernel_launch(void* const* d_in, const int* in_sizes, int n_in,
                              void* d_out, int out_size) {
    const float* x    = (const float*)d_in[0];
    const float* attn = (const float*)d_in[1];
    const float* cw   = (const float*)d_in[2];
    const float* cb   = (const float*)d_in[3];
    float* out = (float*)d_out;

    conv1x1_kernel<<<(BB*HS*HS + 255)/256, 256>>>(x, cw, cb);
    argmax_pool_kernel<<<(BB*SM*SM + 255)/256, 256>>>();
    nz_kernel<<<(BB*CC*QQ*32 + 255)/256, 256>>>(attn);

    static int smem_set = 0;
    size_t smem_bytes = SMEM_FLOATS * sizeof(float);
    if (!smem_set) {
        cudaFuncSetAttribute(matmul_kernel,
                             cudaFuncAttributeMaxDynamicSharedMemorySize,
                             (int)smem_bytes);
        smem_set = 1;
    }
    matmul_kernel<<<dim3(QQ/256, BB*CC), 512, smem_bytes>>>(attn);

    finalize_kernel<<<(BB*SFULL*SFULL + 255)/256, 256>>>(out);

    if (out_size >= OUT_ELEMS + ATTN_ELEMS) {
        cudaMemcpyAsync(out + OUT_ELEMS, attn,
                        (size_t)ATTN_ELEMS * sizeof(float),
                        cudaMemcpyDeviceToDevice);
    }
}

// round 3
// speedup vs baseline: 2.4382x; 2.4382x over previous
#include <cuda_runtime.h>
#include <cuda_bf16.h>
#include <math.h>
#include <stdint.h>

// Problem constants
#define BB     4
#define CIN    256
#define HS     64
#define SFULL  512
#define CC     8
#define SMDIM  128
#define KP     4
#define PP     8
#define LL     256          // K of matmul
#define QQ     4096         // M total per (b,c)
#define PSQ    64           // N of matmul
#define OUT_ELEMS  (BB*CC*SFULL*SFULL)
#define ATTN_ELEMS (BB*CC*QQ*LL)

// -------- scratch (device globals) --------
__device__ float g_y64[BB*CC*HS*HS];                    // conv output
__device__ __nv_bfloat16 g_Ub[BB*CC*PSQ*LL];            // unfold, [bc][p=64][k=256] bf16
__device__ float g_corr[(size_t)BB*CC*QQ*PSQ];          // matmul result [bc][q][p]

// ================= Kernel A: 1x1 conv (256 -> 8) =================
__global__ void conv1x1_kernel(const float* __restrict__ x,
                               const float* __restrict__ w,
                               const float* __restrict__ b) {
    __shared__ float ws[CC*CIN];
    __shared__ float bs[CC];
    for (int i = threadIdx.x; i < CC*CIN; i += blockDim.x) ws[i] = w[i];
    if (threadIdx.x < CC) bs[threadIdx.x] = b[threadIdx.x];
    __syncthreads();

    int pid = blockIdx.x * blockDim.x + threadIdx.x;
    if (pid >= BB*HS*HS) return;
    int bb = pid >> 12;
    int p  = pid & 4095;

    float acc[CC];
#pragma unroll
    for (int c = 0; c < CC; ++c) acc[c] = bs[c];

    const float* xp = x + (size_t)bb*CIN*HS*HS + p;
#pragma unroll 4
    for (int ic = 0; ic < CIN; ++ic) {
        float xv = xp[(size_t)ic*HS*HS];
#pragma unroll
        for (int c = 0; c < CC; ++c) acc[c] += xv * ws[c*CIN + ic];
    }
#pragma unroll
    for (int c = 0; c < CC; ++c)
        g_y64[(bb*CC + c)*HS*HS + p] = acc[c];
}

// ========= Kernel B: bilinear->argmax->4x4 pool -> unfold (bf16, [p][k]) =========
__global__ void argmax_pool_kernel() {
    int idx = blockIdx.x * blockDim.x + threadIdx.x;
    if (idx >= BB*SMDIM*SMDIM) return;
    int bb = idx >> 14;
    int r  = idx & 16383;
    int u  = r >> 7;
    int v  = r & 127;

    const double sc = 63.0 / 511.0;
    int cnt[CC];
#pragma unroll
    for (int c = 0; c < CC; ++c) cnt[c] = 0;

    const float* yb = g_y64 + bb*CC*HS*HS;

#pragma unroll
    for (int i = 0; i < KP; ++i) {
        int s = u*KP + i;
        float ps = (float)(s * sc);
        int lo_s = (int)ps; if (lo_s > 63) lo_s = 63;
        float wsv = ps - (float)lo_s;
        int hi_s = lo_s + 1; if (hi_s > 63) hi_s = 63;
#pragma unroll
        for (int j = 0; j < KP; ++j) {
            int t = v*KP + j;
            float pt = (float)(t * sc);
            int lo_t = (int)pt; if (lo_t > 63) lo_t = 63;
            float wtv = pt - (float)lo_t;
            int hi_t = lo_t + 1; if (hi_t > 63) hi_t = 63;

            float w00 = (1.f-wsv)*(1.f-wtv);
            float w01 = (1.f-wsv)*wtv;
            float w10 = wsv*(1.f-wtv);
            float w11 = wsv*wtv;

            float best = -3.4e38f;
            int bi = 0;
#pragma unroll
            for (int c = 0; c < CC; ++c) {
                const float* yc = yb + c*HS*HS;
                float yv = w00*yc[lo_s*HS + lo_t] + w01*yc[lo_s*HS + hi_t]
                         + w10*yc[hi_s*HS + lo_t] + w11*yc[hi_s*HS + hi_t];
                if (yv > best) { best = yv; bi = c; }
            }
            cnt[bi]++;
        }
    }

    int p = ((u & 7) << 3) | (v & 7);          // pi*8 + pj
    int l = ((u >> 3) << 4) | (v >> 3);        // li*16 + lj
#pragma unroll
    for (int c = 0; c < CC; ++c)
        g_Ub[((bb*CC + c)*PSQ + p)*LL + l] =
            __float2bfloat16((float)cnt[c] * 0.0625f);   // exact in bf16
}

// ============ Kernel D: HMMA bf16 GEMM + fused nz + attn passthrough ============
// Per CTA: C[128,64] = A[128,256] @ U[64,256]^T.  8 warps, each 16 rows x 64 cols.
// Smem: A [128][264] bf16 (padded), B [64][264] bf16 (padded).
#define ALD 264                                  // padded k-stride (bf16 elems)
#define MM_A_BYTES (128*ALD*2)                   // 67584
#define MM_B_BYTES (64*ALD*2)                    // 33792
#define MM_SMEM_TOTAL (MM_A_BYTES + MM_B_BYTES)  // 101376

__global__ void __launch_bounds__(256)
mma_kernel(const float* __restrict__ attn, float* __restrict__ attn_out) {
    extern __shared__ __nv_bfloat16 smb[];
    __nv_bfloat16* As = smb;                 // [128][ALD]
    __nv_bfloat16* Bs = smb + 128*ALD;       // [64][ALD]
    __shared__ float scales[128];
    __shared__ int   cnts[128];

    int tid = threadIdx.x, wid = tid >> 5, lane = tid & 31;
    int bc = blockIdx.y;
    int m0 = blockIdx.x * 128;

    if (tid < 128) cnts[tid] = 0;
    __syncthreads();

    // ---- A tile: load fp32 (coalesced), passthrough-store, nz count, bf16->smem ----
    const float4* Ag = (const float4*)(attn + ((size_t)bc*QQ + m0)*LL);
    float4*       Og = (float4*)(attn_out + ((size_t)bc*QQ + m0)*LL);
#pragma unroll
    for (int it = 0; it < 32; ++it) {
        int flat = it*256 + tid;            // float4 index; 64 per row
        int row  = flat >> 6;
        int k    = (flat & 63) << 2;
        float4 v = Ag[flat];
        Og[flat] = v;
        int c = (v.x != 0.f) + (v.y != 0.f) + (v.z != 0.f) + (v.w != 0.f);
        c = __reduce_add_sync(0xFFFFFFFFu, c);
        if (lane == 0) atomicAdd(&cnts[row], c);
        __nv_bfloat162 h0 = __floats2bfloat162_rn(v.x, v.y);
        __nv_bfloat162 h1 = __floats2bfloat162_rn(v.z, v.w);
        *(uint2*)(As + row*ALD + k) = make_uint2(*(uint32_t*)&h0, *(uint32_t*)&h1);
    }

    // ---- B tile: bf16 from g_Ub -> smem ----
    const uint32_t* Bg = (const uint32_t*)(g_Ub + (size_t)bc*PSQ*LL);
#pragma unroll
    for (int it = 0; it < 32; ++it) {
        int flat = it*256 + tid;            // bf16x2 index; 128 per row
        int row  = flat >> 7;
        int k    = (flat & 127) << 1;
        *(uint32_t*)(Bs + row*ALD + k) = Bg[flat];
    }
    __syncthreads();
    if (tid < 128) scales[tid] = 1.f / ((float)cnts[tid] + 1e-5f);

    // ---- HMMA mainloop: each warp 16 rows x 64 cols, K=256 ----
    int g  = lane >> 2;                     // 0..7
    int tg = lane & 3;                      // 0..3
    int mrow = wid * 16;

    float acc[8][4];
#pragma unroll
    for (int j = 0; j < 8; ++j)
#pragma unroll
        for (int i = 0; i < 4; ++i) acc[j][i] = 0.f;

    const __nv_bfloat16* Ab = As + (mrow + g)*ALD + tg*2;
#pragma unroll 4
    for (int ks = 0; ks < 16; ++ks) {
        int kk = ks * 16;
        uint32_t a0 = *(const uint32_t*)(Ab + kk);
        uint32_t a1 = *(const uint32_t*)(Ab + 8*ALD + kk);
        uint32_t a2 = *(const uint32_t*)(Ab + kk + 8);
        uint32_t a3 = *(const uint32_t*)(Ab + 8*ALD + kk + 8);
#pragma unroll
        for (int j = 0; j < 8; ++j) {
            const __nv_bfloat16* Bb = Bs + (j*8 + g)*ALD + kk + tg*2;
            uint32_t b0 = *(const uint32_t*)(Bb);
            uint32_t b1 = *(const uint32_t*)(Bb + 8);
            asm volatile(
                "mma.sync.aligned.m16n8k16.row.col.f32.bf16.bf16.f32 "
                "{%0,%1,%2,%3}, {%4,%5,%6,%7}, {%8,%9}, {%0,%1,%2,%3};"
                : "+f"(acc[j][0]), "+f"(acc[j][1]), "+f"(acc[j][2]), "+f"(acc[j][3])
                : "r"(a0), "r"(a1), "r"(a2), "r"(a3), "r"(b0), "r"(b1));
        }
    }

    // ---- epilogue: scale by 1/nz, write g_corr ----
    float s0 = scales[mrow + g];
    float s1 = scales[mrow + g + 8];
    float* c0 = g_corr + ((size_t)bc*QQ + m0 + mrow + g)*PSQ + tg*2;
    float* c1 = c0 + 8*PSQ;
#pragma unroll
    for (int j = 0; j < 8; ++j) {
        *(float2*)(c0 + j*8) = make_float2(acc[j][0]*s0, acc[j][1]*s0);
        *(float2*)(c1 + j*8) = make_float2(acc[j][2]*s1, acc[j][3]*s1);
    }
}

// ============ Kernel E: fold + (corr+1)*y + log_softmax ============
__global__ void finalize_kernel(float* __restrict__ out) {
    int idx = blockIdx.x * blockDim.x + threadIdx.x;
    if (idx >= BB*SFULL*SFULL) return;
    int bb = idx >> 18;
    int r  = idx & 262143;
    int s  = r >> 9;
    int t  = r & 511;

    const double sc = 63.0 / 511.0;
    float ps = (float)(s * sc);
    int lo_s = (int)ps; if (lo_s > 63) lo_s = 63;
    float wsv = ps - (float)lo_s;
    int hi_s = lo_s + 1; if (hi_s > 63) hi_s = 63;

    float pt = (float)(t * sc);
    int lo_t = (int)pt; if (lo_t > 63) lo_t = 63;
    float wtv = pt - (float)lo_t;
    int hi_t = lo_t + 1; if (hi_t > 63) hi_t = 63;

    float w00 = (1.f-wsv)*(1.f-wtv);
    float w01 = (1.f-wsv)*wtv;
    float w10 = wsv*(1.f-wtv);
    float w11 = wsv*wtv;

    int q = ((s >> 3) << 6) | (t >> 3);
    int p = ((s & 7) << 3) | (t & 7);

    const float* yb = g_y64 + bb*CC*HS*HS;
    float v[CC];
    float m = -3.4e38f;
#pragma unroll
    for (int c = 0; c < CC; ++c) {
        const float* yc = yb + c*HS*HS;
        float yv = w00*yc[lo_s*HS + lo_t] + w01*yc[lo_s*HS + hi_t]
                 + w10*yc[hi_s*HS + lo_t] + w11*yc[hi_s*HS + hi_t];
        float cr = g_corr[((size_t)(bb*CC + c)*QQ + q)*PSQ + p];
        v[c] = (cr + 1.f) * yv;
        m = fmaxf(m, v[c]);
    }
    float sum = 0.f;
#pragma unroll
    for (int c = 0; c < CC; ++c) sum += __expf(v[c] - m);
    float lse = logf(sum) + m;
#pragma unroll
    for (int c = 0; c < CC; ++c)
        out[(((size_t)(bb*CC + c)) << 18) + (s << 9) + t] = v[c] - lse;
}

// ======================= launch =======================
extern "C" void kernel_launch(void* const* d_in, const int* in_sizes, int n_in,
                              void* d_out, int out_size) {
    const float* x    = (const float*)d_in[0];
    const float* attn = (const float*)d_in[1];
    const float* cw   = (const float*)d_in[2];
    const float* cb   = (const float*)d_in[3];
    float* out = (float*)d_out;

    conv1x1_kernel<<<(BB*HS*HS + 255)/256, 256>>>(x, cw, cb);
    argmax_pool_kernel<<<(BB*SMDIM*SMDIM + 255)/256, 256>>>();

    static int smem_set = 0;
    if (!smem_set) {
        cudaFuncSetAttribute(mma_kernel,
                             cudaFuncAttributeMaxDynamicSharedMemorySize,
                             MM_SMEM_TOTAL);
        smem_set = 1;
    }
    mma_kernel<<<dim3(QQ/128, BB*CC), 256, MM_SMEM_TOTAL>>>(attn, out + OUT_ELEMS);

    finalize_kernel<<<(BB*SFULL*SFULL + 255)/256, 256>>>(out);
}

// round 4
// speedup vs baseline: 3.0916x; 1.2680x over previous
#include <cuda_runtime.h>
#include <cuda_bf16.h>
#include <math.h>
#include <stdint.h>

// Problem constants
#define BB     4
#define CIN    256
#define HS     64
#define SFULL  512
#define CC     8
#define SMDIM  128
#define KP     4
#define PP     8
#define LL     256          // K of matmul
#define QQ     4096         // M total per (b,c)
#define PSQ    64           // N of matmul
#define OUT_ELEMS  (BB*CC*SFULL*SFULL)
#define ATTN_ELEMS (BB*CC*QQ*LL)

// -------- scratch (device globals) --------
__device__ float g_y64[BB*CC*HS*HS];                    // conv output
__device__ __nv_bfloat16 g_Ub[BB*CC*PSQ*LL];            // unfold, [bc][p=64][k=256] bf16
__device__ float g_corr[(size_t)BB*CC*SFULL*SFULL];     // corr, SPATIAL [bc][s][t]

// ================= Kernel A: 1x1 conv (256 -> 8), ic-split x4 =================
__global__ void __launch_bounds__(256)
conv1x1_kernel(const float* __restrict__ x,
               const float* __restrict__ w,
               const float* __restrict__ b) {
    __shared__ float ws[CC*CIN];
    __shared__ float sacc[64*9];           // padded stride 9 to spread atomics
    int tid = threadIdx.x;
    for (int i = tid; i < CC*CIN; i += 256) ws[i] = w[i];
    for (int i = tid; i < 64*9; i += 256) sacc[i] = 0.f;
    __syncthreads();

    int px  = tid & 63;
    int icq = tid >> 6;                    // 0..3
    int pid = blockIdx.x*64 + px;          // 0..16383
    int bb  = pid >> 12;
    int p   = pid & 4095;

    float acc[CC];
#pragma unroll
    for (int c = 0; c < CC; ++c) acc[c] = 0.f;

    const float* xp = x + (size_t)bb*CIN*HS*HS + (size_t)icq*64*HS*HS + p;
#pragma unroll 8
    for (int ic = 0; ic < 64; ++ic) {
        float xv = xp[(size_t)ic*HS*HS];
        int icg = icq*64 + ic;
#pragma unroll
        for (int c = 0; c < CC; ++c) acc[c] += xv * ws[c*CIN + icg];
    }
#pragma unroll
    for (int c = 0; c < CC; ++c) atomicAdd(&sacc[px*9 + c], acc[c]);
    __syncthreads();

    if (tid < 64) {
        int pid2 = blockIdx.x*64 + tid;
        int bb2  = pid2 >> 12;
        int p2   = pid2 & 4095;
#pragma unroll
        for (int c = 0; c < CC; ++c)
            g_y64[(bb2*CC + c)*HS*HS + p2] = sacc[tid*9 + c] + b[c];
    }
}

// ========= Kernel B: bilinear->argmax->4x4 pool -> unfold (bf16, [p][k]) =========
__global__ void argmax_pool_kernel() {
    int idx = blockIdx.x * blockDim.x + threadIdx.x;
    if (idx >= BB*SMDIM*SMDIM) return;
    int bb = idx >> 14;
    int r  = idx & 16383;
    int u  = r >> 7;
    int v  = r & 127;

    const double sc = 63.0 / 511.0;
    int cnt[CC];
#pragma unroll
    for (int c = 0; c < CC; ++c) cnt[c] = 0;

    const float* yb = g_y64 + bb*CC*HS*HS;

#pragma unroll
    for (int i = 0; i < KP; ++i) {
        int s = u*KP + i;
        float ps = (float)(s * sc);
        int lo_s = (int)ps; if (lo_s > 63) lo_s = 63;
        float wsv = ps - (float)lo_s;
        int hi_s = lo_s + 1; if (hi_s > 63) hi_s = 63;
#pragma unroll
        for (int j = 0; j < KP; ++j) {
            int t = v*KP + j;
            float pt = (float)(t * sc);
            int lo_t = (int)pt; if (lo_t > 63) lo_t = 63;
            float wtv = pt - (float)lo_t;
            int hi_t = lo_t + 1; if (hi_t > 63) hi_t = 63;

            float w00 = (1.f-wsv)*(1.f-wtv);
            float w01 = (1.f-wsv)*wtv;
            float w10 = wsv*(1.f-wtv);
            float w11 = wsv*wtv;

            float best = -3.4e38f;
            int bi = 0;
#pragma unroll
            for (int c = 0; c < CC; ++c) {
                const float* yc = yb + c*HS*HS;
                float yv = w00*yc[lo_s*HS + lo_t] + w01*yc[lo_s*HS + hi_t]
                         + w10*yc[hi_s*HS + lo_t] + w11*yc[hi_s*HS + hi_t];
                if (yv > best) { best = yv; bi = c; }
            }
            cnt[bi]++;
        }
    }

    int p = ((u & 7) << 3) | (v & 7);          // pi*8 + pj
    int l = ((u >> 3) << 4) | (v >> 3);        // li*16 + lj
#pragma unroll
    for (int c = 0; c < CC; ++c)
        g_Ub[((bb*CC + c)*PSQ + p)*LL + l] =
            __float2bfloat16((float)cnt[c] * 0.0625f);   // exact in bf16
}

// ============ Kernel D: HMMA bf16 GEMM + fused nz + attn passthrough ============
// Per CTA: C[64,64] = A[64,256] @ U[64,256]^T.  4 warps, each 16 rows x 64 cols.
// Smem: A [64][264] bf16 (padded), B [64][264] bf16 (padded) = 67.6 KB -> 3 CTAs/SM.
// Epilogue folds directly into spatial [bc][s][t] layout.
#define ALD 264
#define MM_A_BYTES (64*ALD*2)                    // 33792
#define MM_B_BYTES (64*ALD*2)                    // 33792
#define MM_SMEM_TOTAL (MM_A_BYTES + MM_B_BYTES)  // 67584

__global__ void __launch_bounds__(128)
mma_kernel(const float* __restrict__ attn, float* __restrict__ attn_out) {
    extern __shared__ __nv_bfloat16 smb[];
    __nv_bfloat16* As = smb;                 // [64][ALD]
    __nv_bfloat16* Bs = smb + 64*ALD;        // [64][ALD]
    __shared__ float scales[64];
    __shared__ int   cnts[64];

    int tid = threadIdx.x, wid = tid >> 5, lane = tid & 31;
    int bc = blockIdx.y;
    int m0 = blockIdx.x * 64;

    if (tid < 64) cnts[tid] = 0;
    __syncthreads();

    // ---- A tile: fp32 load (coalesced), passthrough, nz count, bf16->smem ----
    const float4* Ag = (const float4*)(attn + ((size_t)bc*QQ + m0)*LL);
    float4*       Og = (float4*)(attn_out + ((size_t)bc*QQ + m0)*LL);
#pragma unroll
    for (int it = 0; it < 32; ++it) {
        int flat = it*128 + tid;            // float4 index; 64 per row
        int row  = flat >> 6;               // 0..63, warp-uniform
        int k    = (flat & 63) << 2;
        float4 v = Ag[flat];
        Og[flat] = v;
        int c = (v.x != 0.f) + (v.y != 0.f) + (v.z != 0.f) + (v.w != 0.f);
        c = __reduce_add_sync(0xFFFFFFFFu, c);
        if (lane == 0) atomicAdd(&cnts[row], c);
        __nv_bfloat162 h0 = __floats2bfloat162_rn(v.x, v.y);
        __nv_bfloat162 h1 = __floats2bfloat162_rn(v.z, v.w);
        *(uint2*)(As + row*ALD + k) = make_uint2(*(uint32_t*)&h0, *(uint32_t*)&h1);
    }

    // ---- B tile: bf16 from g_Ub (uint4) -> smem ----
    const uint4* Bg = (const uint4*)(g_Ub + (size_t)bc*PSQ*LL);
#pragma unroll
    for (int it = 0; it < 16; ++it) {
        int flat = it*128 + tid;            // uint4 index; 32 per row
        int row  = flat >> 5;
        int k    = (flat & 31) << 3;
        *(uint4*)(Bs + row*ALD + k) = Bg[flat];
    }
    __syncthreads();
    if (tid < 64) scales[tid] = 1.f / ((float)cnts[tid] + 1e-5f);

    // ---- HMMA mainloop: each warp 16 rows x 64 cols, K=256 ----
    int g  = lane >> 2;                     // 0..7
    int tg = lane & 3;                      // 0..3
    int mrow = wid * 16;

    float acc[8][4];
#pragma unroll
    for (int j = 0; j < 8; ++j)
#pragma unroll
        for (int i = 0; i < 4; ++i) acc[j][i] = 0.f;

    const __nv_bfloat16* Ab = As + (mrow + g)*ALD + tg*2;
#pragma unroll 4
    for (int ks = 0; ks < 16; ++ks) {
        int kk = ks * 16;
        uint32_t a0 = *(const uint32_t*)(Ab + kk);
        uint32_t a1 = *(const uint32_t*)(Ab + 8*ALD + kk);
        uint32_t a2 = *(const uint32_t*)(Ab + kk + 8);
        uint32_t a3 = *(const uint32_t*)(Ab + 8*ALD + kk + 8);
#pragma unroll
        for (int j = 0; j < 8; ++j) {
            const __nv_bfloat16* Bb = Bs + (j*8 + g)*ALD + kk + tg*2;
            uint32_t b0 = *(const uint32_t*)(Bb);
            uint32_t b1 = *(const uint32_t*)(Bb + 8);
            asm volatile(
                "mma.sync.aligned.m16n8k16.row.col.f32.bf16.bf16.f32 "
                "{%0,%1,%2,%3}, {%4,%5,%6,%7}, {%8,%9}, {%0,%1,%2,%3};"
                : "+f"(acc[j][0]), "+f"(acc[j][1]), "+f"(acc[j][2]), "+f"(acc[j][3])
                : "r"(a0), "r"(a1), "r"(a2), "r"(a3), "r"(b0), "r"(b1));
        }
    }

    // ---- epilogue: scale by 1/nz, fold to spatial [bc][s][t] ----
    // q = m0+mrow+g (+8), p = j*8 + tg*2 ; s = (q>>6)*8 + j ; t = (q&63)*8 + tg*2
    int q0r = m0 + mrow + g;
    int q1r = q0r + 8;
    float s0 = scales[mrow + g];
    float s1 = scales[mrow + g + 8];
    float* base = g_corr + ((size_t)bc << 18);
    int sh0 = (q0r >> 6) * 8;               // same for q1r (mrow+g+8 <= 63)
    int t0  = ((q0r & 63) << 3) + tg*2;
    int t1  = ((q1r & 63) << 3) + tg*2;
#pragma unroll
    for (int j = 0; j < 8; ++j) {
        int srow = (sh0 + j) << 9;
        *(float2*)(base + srow + t0) = make_float2(acc[j][0]*s0, acc[j][1]*s0);
        *(float2*)(base + srow + t1) = make_float2(acc[j][2]*s1, acc[j][3]*s1);
    }
}

// ============ Kernel E: (corr+1)*y + log_softmax, 4 pixels/thread ============
__global__ void __launch_bounds__(256)
finalize_kernel(float* __restrict__ out) {
    int idx = blockIdx.x * blockDim.x + threadIdx.x;   // BB*512*128 threads
    if (idx >= BB*SFULL*128) return;
    int bb = idx >> 16;
    int r  = idx & 65535;
    int s  = r >> 7;
    int t0 = (r & 127) << 2;

    const double sc = 63.0 / 511.0;
    float ps = (float)(s * sc);
    int lo_s = (int)ps; if (lo_s > 63) lo_s = 63;
    float wsv = ps - (float)lo_s;
    int hi_s = lo_s + 1; if (hi_s > 63) hi_s = 63;

    int lo_t[4], hi_t[4];
    float wt[4];
#pragma unroll
    for (int i = 0; i < 4; ++i) {
        float pt = (float)((t0 + i) * sc);
        int lt = (int)pt; if (lt > 63) lt = 63;
        wt[i] = pt - (float)lt;
        lo_t[i] = lt;
        hi_t[i] = lt + 1; if (hi_t[i] > 63) hi_t[i] = 63;
    }

    const float* yb = g_y64 + bb*CC*HS*HS;
    float v[CC][4];
    float m[4] = {-3.4e38f, -3.4e38f, -3.4e38f, -3.4e38f};
#pragma unroll
    for (int c = 0; c < CC; ++c) {
        const float* ylo = yb + c*HS*HS + lo_s*HS;
        const float* yhi = yb + c*HS*HS + hi_s*HS;
        float4 cr = *(const float4*)(g_corr + (((size_t)(bb*CC + c)) << 18)
                                     + (s << 9) + t0);
        float crv[4] = {cr.x, cr.y, cr.z, cr.w};
#pragma unroll
        for (int i = 0; i < 4; ++i) {
            float ytop = ylo[lo_t[i]] + wt[i]*(ylo[hi_t[i]] - ylo[lo_t[i]]);
            float ybot = yhi[lo_t[i]] + wt[i]*(yhi[hi_t[i]] - yhi[lo_t[i]]);
            float yv = ytop + wsv*(ybot - ytop);
            v[c][i] = (crv[i] + 1.f) * yv;
            m[i] = fmaxf(m[i], v[c][i]);
        }
    }
    float lse[4];
#pragma unroll
    for (int i = 0; i < 4; ++i) {
        float sum = 0.f;
#pragma unroll
        for (int c = 0; c < CC; ++c) sum += __expf(v[c][i] - m[i]);
        lse[i] = logf(sum) + m[i];
    }
#pragma unroll
    for (int c = 0; c < CC; ++c) {
        float4 o;
        o.x = v[c][0] - lse[0];
        o.y = v[c][1] - lse[1];
        o.z = v[c][2] - lse[2];
        o.w = v[c][3] - lse[3];
        *(float4*)(out + (((size_t)(bb*CC + c)) << 18) + (s << 9) + t0) = o;
    }
}

// ======================= launch =======================
extern "C" void kernel_launch(void* const* d_in, const int* in_sizes, int n_in,
                              void* d_out, int out_size) {
    const float* x    = (const float*)d_in[0];
    const float* attn = (const float*)d_in[1];
    const float* cw   = (const float*)d_in[2];
    const float* cb   = (const float*)d_in[3];
    float* out = (float*)d_out;

    conv1x1_kernel<<<BB*HS*HS/64, 256>>>(x, cw, cb);
    argmax_pool_kernel<<<(BB*SMDIM*SMDIM + 255)/256, 256>>>();

    static int smem_set = 0;
    if (!smem_set) {
        cudaFuncSetAttribute(mma_kernel,
                             cudaFuncAttributeMaxDynamicSharedMemorySize,
                             MM_SMEM_TOTAL);
        smem_set = 1;
    }
    mma_kernel<<<dim3(QQ/64, BB*CC), 128, MM_SMEM_TOTAL>>>(attn, out + OUT_ELEMS);

    finalize_kernel<<<(BB*SFULL*128 + 255)/256, 256>>>(out);
}

// round 5
// speedup vs baseline: 3.0967x; 1.0016x over previous
#include <cuda_runtime.h>
#include <cuda_bf16.h>
#include <math.h>
#include <stdint.h>

// Problem constants
#define BB     4
#define CIN    256
#define HS     64
#define SFULL  512
#define CC     8
#define SMDIM  128
#define KP     4
#define PP     8
#define LL     256          // K of matmul
#define QQ     4096         // M total per (b,c)
#define PSQ    64           // N of matmul
#define OUT_ELEMS  (BB*CC*SFULL*SFULL)
#define ATTN_ELEMS (BB*CC*QQ*LL)

// -------- scratch (device globals) --------
__device__ float g_y64[BB*CC*HS*HS];                    // conv output
__device__ __nv_bfloat16 g_Ub[BB*CC*PSQ*LL];            // unfold, [bc][p=64][k=256] bf16

// ================= Kernel A: 1x1 conv (256 -> 8), ic-split x4 =================
__global__ void __launch_bounds__(256)
conv1x1_kernel(const float* __restrict__ x,
               const float* __restrict__ w,
               const float* __restrict__ b) {
    __shared__ float ws[CC*CIN];
    __shared__ float sacc[64*9];
    int tid = threadIdx.x;
    for (int i = tid; i < CC*CIN; i += 256) ws[i] = w[i];
    for (int i = tid; i < 64*9; i += 256) sacc[i] = 0.f;
    __syncthreads();

    int px  = tid & 63;
    int icq = tid >> 6;
    int pid = blockIdx.x*64 + px;
    int bb  = pid >> 12;
    int p   = pid & 4095;

    float acc[CC];
#pragma unroll
    for (int c = 0; c < CC; ++c) acc[c] = 0.f;

    const float* xp = x + (size_t)bb*CIN*HS*HS + (size_t)icq*64*HS*HS + p;
#pragma unroll 8
    for (int ic = 0; ic < 64; ++ic) {
        float xv = xp[(size_t)ic*HS*HS];
        int icg = icq*64 + ic;
#pragma unroll
        for (int c = 0; c < CC; ++c) acc[c] += xv * ws[c*CIN + icg];
    }
#pragma unroll
    for (int c = 0; c < CC; ++c) atomicAdd(&sacc[px*9 + c], acc[c]);
    __syncthreads();

    if (tid < 64) {
        int pid2 = blockIdx.x*64 + tid;
        int bb2  = pid2 >> 12;
        int p2   = pid2 & 4095;
#pragma unroll
        for (int c = 0; c < CC; ++c)
            g_y64[(bb2*CC + c)*HS*HS + p2] = sacc[tid*9 + c] + b[c];
    }
}

// ========= Kernel B: bilinear->argmax->4x4 pool -> unfold (bf16, [p][k]) =========
__global__ void argmax_pool_kernel() {
    int idx = blockIdx.x * blockDim.x + threadIdx.x;
    if (idx >= BB*SMDIM*SMDIM) return;
    int bb = idx >> 14;
    int r  = idx & 16383;
    int u  = r >> 7;
    int v  = r & 127;

    const double sc = 63.0 / 511.0;
    int cnt[CC];
#pragma unroll
    for (int c = 0; c < CC; ++c) cnt[c] = 0;

    const float* yb = g_y64 + bb*CC*HS*HS;

#pragma unroll
    for (int i = 0; i < KP; ++i) {
        int s = u*KP + i;
        float ps = (float)(s * sc);
        int lo_s = (int)ps; if (lo_s > 63) lo_s = 63;
        float wsv = ps - (float)lo_s;
        int hi_s = lo_s + 1; if (hi_s > 63) hi_s = 63;
#pragma unroll
        for (int j = 0; j < KP; ++j) {
            int t = v*KP + j;
            float pt = (float)(t * sc);
            int lo_t = (int)pt; if (lo_t > 63) lo_t = 63;
            float wtv = pt - (float)lo_t;
            int hi_t = lo_t + 1; if (hi_t > 63) hi_t = 63;

            float w00 = (1.f-wsv)*(1.f-wtv);
            float w01 = (1.f-wsv)*wtv;
            float w10 = wsv*(1.f-wtv);
            float w11 = wsv*wtv;

            float best = -3.4e38f;
            int bi = 0;
#pragma unroll
            for (int c = 0; c < CC; ++c) {
                const float* yc = yb + c*HS*HS;
                float yv = w00*yc[lo_s*HS + lo_t] + w01*yc[lo_s*HS + hi_t]
                         + w10*yc[hi_s*HS + lo_t] + w11*yc[hi_s*HS + hi_t];
                if (yv > best) { best = yv; bi = c; }
            }
            cnt[bi]++;
        }
    }

    int p = ((u & 7) << 3) | (v & 7);
    int l = ((u >> 3) << 4) | (v >> 3);
#pragma unroll
    for (int c = 0; c < CC; ++c)
        g_Ub[((bb*CC + c)*PSQ + p)*LL + l] =
            __float2bfloat16((float)cnt[c] * 0.0625f);
}

// ====== Kernel D: fully fused GEMM(8 classes) + nz + passthrough + softmax ======
// One CTA per (b, mtile of 64 q-rows) -> 8 complete spatial rows, all classes.
// 512 threads = 16 warps; warp (wr=wid&3, wc=wid>>2) owns C tile rows wr*16..+15,
// cols wc*16..+15. Per-class C fragments kept in registers: corr[8][2][4].
#define ALD 264
#define DSMEM_AB   (2*64*ALD*2)                // As + Bs bytes = 67584
#define DSMEM_YROW (CC*8*64*4)                 // 16384
#define FUSED_SMEM (DSMEM_AB + DSMEM_YROW)     // 83968

__global__ void __launch_bounds__(512)
fused_kernel(const float* __restrict__ attn, float* __restrict__ out,
             float* __restrict__ attn_out) {
    extern __shared__ char dsm[];
    __nv_bfloat16* As = (__nv_bfloat16*)dsm;            // [64][ALD]
    __nv_bfloat16* Bs = As + 64*ALD;                    // [64][ALD]
    float* yrow = (float*)(dsm + DSMEM_AB);             // [8c][8sr][64]
    __shared__ float scales[64];
    __shared__ int   cnts[64];

    const int tid  = threadIdx.x;
    const int wid  = tid >> 5, lane = tid & 31;
    const int g    = lane >> 2, tg = lane & 3;
    const int wr   = wid & 3,  wc  = wid >> 2;
    const int mrow = wr * 16;
    const int mt   = blockIdx.x;                        // 0..63
    const int b    = blockIdx.y;                        // 0..3
    const int m0   = mt * 64;
    const double sc = 63.0 / 511.0;

    // ---- yrow precompute: s-interpolated y rows for this CTA's 8 s-rows ----
#pragma unroll
    for (int it = 0; it < 8; ++it) {
        int i   = it*512 + tid;            // 0..4095
        int c   = i >> 9;
        int sr  = (i >> 6) & 7;
        int col = i & 63;
        int s   = mt*8 + sr;
        float ps = (float)(s * sc);
        int ls = (int)ps; if (ls > 63) ls = 63;
        float wsv = ps - (float)ls;
        int hs = ls + 1; if (hs > 63) hs = 63;
        const float* yc = g_y64 + (b*CC + c)*HS*HS;
        float lo = yc[ls*HS + col], hi = yc[hs*HS + col];
        yrow[i] = lo + wsv*(hi - lo);
    }

    float corr[CC][2][4];
#pragma unroll
    for (int c = 0; c < CC; ++c)
#pragma unroll
        for (int j = 0; j < 2; ++j)
#pragma unroll
            for (int i = 0; i < 4; ++i) corr[c][j][i] = 0.f;

    // ---- class loop ----
#pragma unroll
    for (int c = 0; c < CC; ++c) {
        int bc = b*CC + c;
        __syncthreads();                   // protect As/Bs + cnts reuse
        if (tid < 64) cnts[tid] = 0;
        __syncthreads();

        // A tile: fp32 load, passthrough, nz count, bf16 -> smem
        const float4* Ag = (const float4*)(attn + ((size_t)bc*QQ + m0)*LL);
        float4*       Og = (float4*)(attn_out + ((size_t)bc*QQ + m0)*LL);
#pragma unroll
        for (int it = 0; it < 8; ++it) {
            int flat = it*512 + tid;       // float4 idx; 64 per row
            int row  = flat >> 6;          // warp-uniform
            int k    = (flat & 63) << 2;
            float4 v = Ag[flat];
            Og[flat] = v;
            int cn = (v.x != 0.f) + (v.y != 0.f) + (v.z != 0.f) + (v.w != 0.f);
            cn = __reduce_add_sync(0xFFFFFFFFu, cn);
            if (lane == 0) atomicAdd(&cnts[row], cn);
            __nv_bfloat162 h0 = __floats2bfloat162_rn(v.x, v.y);
            __nv_bfloat162 h1 = __floats2bfloat162_rn(v.z, v.w);
            *(uint2*)(As + row*ALD + k) = make_uint2(*(uint32_t*)&h0, *(uint32_t*)&h1);
        }
        // B tile
        const uint4* Bg = (const uint4*)(g_Ub + (size_t)bc*PSQ*LL);
#pragma unroll
        for (int it = 0; it < 4; ++it) {
            int flat = it*512 + tid;       // uint4 idx; 32 per row
            int row  = flat >> 5;
            int k    = (flat & 31) << 3;
            *(uint4*)(Bs + row*ALD + k) = Bg[flat];
        }
        __syncthreads();
        if (tid < 64) scales[tid] = 1.f / ((float)cnts[tid] + 1e-5f);
        __syncthreads();

        // HMMA: warp computes 16x16 C tile for class c
        const __nv_bfloat16* Ab = As + (mrow + g)*ALD + tg*2;
#pragma unroll 4
        for (int ks = 0; ks < 16; ++ks) {
            int kk = ks * 16;
            uint32_t a0 = *(const uint32_t*)(Ab + kk);
            uint32_t a1 = *(const uint32_t*)(Ab + 8*ALD + kk);
            uint32_t a2 = *(const uint32_t*)(Ab + kk + 8);
            uint32_t a3 = *(const uint32_t*)(Ab + 8*ALD + kk + 8);
#pragma unroll
            for (int j = 0; j < 2; ++j) {
                const __nv_bfloat16* Bb = Bs + (wc*16 + j*8 + g)*ALD + kk + tg*2;
                uint32_t b0 = *(const uint32_t*)(Bb);
                uint32_t b1 = *(const uint32_t*)(Bb + 8);
                asm volatile(
                    "mma.sync.aligned.m16n8k16.row.col.f32.bf16.bf16.f32 "
                    "{%0,%1,%2,%3}, {%4,%5,%6,%7}, {%8,%9}, {%0,%1,%2,%3};"
                    : "+f"(corr[c][j][0]), "+f"(corr[c][j][1]),
                      "+f"(corr[c][j][2]), "+f"(corr[c][j][3])
                    : "r"(a0), "r"(a1), "r"(a2), "r"(a3), "r"(b0), "r"(b1));
            }
        }
        // scale by 1/nz for this class
        float s0 = scales[mrow + g];
        float s1 = scales[mrow + g + 8];
#pragma unroll
        for (int j = 0; j < 2; ++j) {
            corr[c][j][0] *= s0; corr[c][j][1] *= s0;
            corr[c][j][2] *= s1; corr[c][j][3] *= s1;
        }
    }

    // ---- fused epilogue: (corr+1)*y, log_softmax over classes, write out ----
#pragma unroll
    for (int r = 0; r < 2; ++r) {
        int qrow = mrow + g + r*8;         // local q row 0..63
        int t0 = qrow*8 + tg*2;
        int t1 = t0 + 1;
        float pt0 = (float)(t0 * sc);
        int lt0 = (int)pt0; if (lt0 > 63) lt0 = 63;
        float wt0 = pt0 - (float)lt0;
        int ht0 = lt0 + 1; if (ht0 > 63) ht0 = 63;
        float pt1 = (float)(t1 * sc);
        int lt1 = (int)pt1; if (lt1 > 63) lt1 = 63;
        float wt1 = pt1 - (float)lt1;
        int ht1 = lt1 + 1; if (ht1 > 63) ht1 = 63;

#pragma unroll
        for (int j = 0; j < 2; ++j) {
            int sr = wc*2 + j;
            float v0[CC], v1[CC];
            float m0v = -3.4e38f, m1v = -3.4e38f;
#pragma unroll
            for (int c = 0; c < CC; ++c) {
                const float* yr = yrow + (c*8 + sr)*64;
                float a0 = yr[lt0];
                float y0 = a0 + wt0*(yr[ht0] - a0);
                float a1 = yr[lt1];
                float y1 = a1 + wt1*(yr[ht1] - a1);
                v0[c] = (corr[c][j][r*2+0] + 1.f) * y0;
                v1[c] = (corr[c][j][r*2+1] + 1.f) * y1;
                m0v = fmaxf(m0v, v0[c]);
                m1v = fmaxf(m1v, v1[c]);
            }
            float su0 = 0.f, su1 = 0.f;
#pragma unroll
            for (int c = 0; c < CC; ++c) {
                su0 += __expf(v0[c] - m0v);
                su1 += __expf(v1[c] - m1v);
            }
            float lse0 = logf(su0) + m0v;
            float lse1 = logf(su1) + m1v;
            int s_glob = mt*8 + sr;
#pragma unroll
            for (int c = 0; c < CC; ++c) {
                float* op = out + (((size_t)(b*CC + c)) << 18) + (s_glob << 9) + t0;
                *(float2*)op = make_float2(v0[c] - lse0, v1[c] - lse1);
            }
        }
    }
}

// ======================= launch =======================
extern "C" void kernel_launch(void* const* d_in, const int* in_sizes, int n_in,
                              void* d_out, int out_size) {
    const float* x    = (const float*)d_in[0];
    const float* attn = (const float*)d_in[1];
    const float* cw   = (const float*)d_in[2];
    const float* cb   = (const float*)d_in[3];
    float* out = (float*)d_out;

    conv1x1_kernel<<<BB*HS*HS/64, 256>>>(x, cw, cb);
    argmax_pool_kernel<<<(BB*SMDIM*SMDIM + 255)/256, 256>>>();

    static int smem_set = 0;
    if (!smem_set) {
        cudaFuncSetAttribute(fused_kernel,
                             cudaFuncAttributeMaxDynamicSharedMemorySize,
                             FUSED_SMEM);
        smem_set = 1;
    }
    fused_kernel<<<dim3(QQ/64, BB), 512, FUSED_SMEM>>>(attn, out, out + OUT_ELEMS);
}

// round 6
// speedup vs baseline: 3.4395x; 1.1107x over previous
#include <cuda_runtime.h>
#include <cuda_bf16.h>
#include <math.h>
#include <stdint.h>

// Problem constants
#define BB     4
#define CIN    256
#define HS     64
#define SFULL  512
#define CC     8
#define SMDIM  128
#define KP     4
#define PP     8
#define LL     256          // K of matmul
#define QQ     4096         // M total per (b,c)
#define PSQ    64           // N of matmul
#define OUT_ELEMS  (BB*CC*SFULL*SFULL)
#define ATTN_ELEMS (BB*CC*QQ*LL)

// -------- scratch (device globals) --------
__device__ float g_y64[BB*CC*HS*HS];                    // conv output
__device__ __nv_bfloat16 g_Ub[BB*CC*PSQ*LL];            // unfold, [bc][p=64][k=256] bf16

// ================= Kernel A: 1x1 conv (256 -> 8), 8-way ic split =================
__global__ void __launch_bounds__(256)
conv1x1_kernel(const float* __restrict__ x,
               const float* __restrict__ w,
               const float* __restrict__ b) {
    __shared__ float ws[CC*CIN];
    __shared__ float sacc[32*9];
    int tid = threadIdx.x;
    for (int i = tid; i < CC*CIN; i += 256) ws[i] = w[i];
    if (tid < 32*9/2) { sacc[tid] = 0.f; sacc[tid + 144] = 0.f; }
    __syncthreads();

    int px  = tid & 31;
    int icq = tid >> 5;                    // 0..7, 32 ic each
    int pid = blockIdx.x*32 + px;          // 0..16383
    int bb  = pid >> 12;
    int p   = pid & 4095;

    float acc[CC];
#pragma unroll
    for (int c = 0; c < CC; ++c) acc[c] = 0.f;

    const float* xp = x + (size_t)bb*CIN*HS*HS + (size_t)icq*32*HS*HS + p;
#pragma unroll 8
    for (int ic = 0; ic < 32; ++ic) {
        float xv = xp[(size_t)ic*HS*HS];
        int icg = icq*32 + ic;
#pragma unroll
        for (int c = 0; c < CC; ++c) acc[c] += xv * ws[c*CIN + icg];
    }
#pragma unroll
    for (int c = 0; c < CC; ++c) atomicAdd(&sacc[px*9 + c], acc[c]);
    __syncthreads();

    if (tid < 32) {
        int pid2 = blockIdx.x*32 + tid;
        int bb2  = pid2 >> 12;
        int p2   = pid2 & 4095;
#pragma unroll
        for (int c = 0; c < CC; ++c)
            g_y64[(bb2*CC + c)*HS*HS + p2] = sacc[tid*9 + c] + b[c];
    }
}

// ========= Kernel B: bilinear->argmax->4x4 pool -> unfold (bf16, [p][k]) =========
__global__ void argmax_pool_kernel() {
    int idx = blockIdx.x * blockDim.x + threadIdx.x;
    if (idx >= BB*SMDIM*SMDIM) return;
    int bb = idx >> 14;
    int r  = idx & 16383;
    int u  = r >> 7;
    int v  = r & 127;

    const double sc = 63.0 / 511.0;
    int cnt[CC];
#pragma unroll
    for (int c = 0; c < CC; ++c) cnt[c] = 0;

    const float* yb = g_y64 + bb*CC*HS*HS;

#pragma unroll
    for (int i = 0; i < KP; ++i) {
        int s = u*KP + i;
        float ps = (float)(s * sc);
        int lo_s = (int)ps; if (lo_s > 63) lo_s = 63;
        float wsv = ps - (float)lo_s;
        int hi_s = lo_s + 1; if (hi_s > 63) hi_s = 63;
#pragma unroll
        for (int j = 0; j < KP; ++j) {
            int t = v*KP + j;
            float pt = (float)(t * sc);
            int lo_t = (int)pt; if (lo_t > 63) lo_t = 63;
            float wtv = pt - (float)lo_t;
            int hi_t = lo_t + 1; if (hi_t > 63) hi_t = 63;

            float w00 = (1.f-wsv)*(1.f-wtv);
            float w01 = (1.f-wsv)*wtv;
            float w10 = wsv*(1.f-wtv);
            float w11 = wsv*wtv;

            float best = -3.4e38f;
            int bi = 0;
#pragma unroll
            for (int c = 0; c < CC; ++c) {
                const float* yc = yb + c*HS*HS;
                float yv = w00*yc[lo_s*HS + lo_t] + w01*yc[lo_s*HS + hi_t]
                         + w10*yc[hi_s*HS + lo_t] + w11*yc[hi_s*HS + hi_t];
                if (yv > best) { best = yv; bi = c; }
            }
            cnt[bi]++;
        }
    }

    int p = ((u & 7) << 3) | (v & 7);
    int l = ((u >> 3) << 4) | (v >> 3);
#pragma unroll
    for (int c = 0; c < CC; ++c)
        g_Ub[((bb*CC + c)*PSQ + p)*LL + l] =
            __float2bfloat16((float)cnt[c] * 0.0625f);
}

// ====== Kernel D: fused GEMM(8 classes) + nz + passthrough + softmax ======
// One CTA per (b, mtile of 32 q-rows). 256 threads = 8 warps (2 x 4);
// warp (wr, wc) owns C rows wr*16..+15, cols wc*16..+15, for all 8 classes.
#define ALD 264
#define DSMEM_A    (32*ALD*2)                  // 16896
#define DSMEM_B    (64*ALD*2)                  // 33792
#define DSMEM_YROW (CC*8*64*4)                 // 16384
#define FUSED_SMEM (DSMEM_A + DSMEM_B + DSMEM_YROW)   // 67072

__global__ void __launch_bounds__(256, 2)
fused_kernel(const float* __restrict__ attn, float* __restrict__ out,
             float* __restrict__ attn_out) {
    extern __shared__ char dsm[];
    __nv_bfloat16* As = (__nv_bfloat16*)dsm;            // [32][ALD]
    __nv_bfloat16* Bs = As + 32*ALD;                    // [64][ALD]
    float* yrow = (float*)(dsm + DSMEM_A + DSMEM_B);    // [8c][8sr][64]
    __shared__ float scales[32];
    __shared__ int   cnts[32];

    const int tid  = threadIdx.x;
    const int wid  = tid >> 5, lane = tid & 31;
    const int g    = lane >> 2, tg = lane & 3;
    const int wr   = wid & 1,  wc  = wid >> 1;          // 2 x 4 warp grid
    const int mrow = wr * 16;
    const int mt   = blockIdx.x;                        // 0..127
    const int b    = blockIdx.y;                        // 0..3
    const int m0   = mt * 32;
    const int sh0  = (mt >> 1) * 8;                     // CTA's 8 s-rows
    const double sc = 63.0 / 511.0;

    // ---- yrow precompute ----
#pragma unroll
    for (int it = 0; it < 16; ++it) {
        int i   = it*256 + tid;            // 0..4095
        int c   = i >> 9;
        int sr  = (i >> 6) & 7;
        int col = i & 63;
        int s   = sh0 + sr;
        float ps = (float)(s * sc);
        int ls = (int)ps; if (ls > 63) ls = 63;
        float wsv = ps - (float)ls;
        int hs = ls + 1; if (hs > 63) hs = 63;
        const float* yc = g_y64 + (b*CC + c)*HS*HS;
        float lo = yc[ls*HS + col], hi = yc[hs*HS + col];
        yrow[i] = lo + wsv*(hi - lo);
    }

    float corr[CC][2][4];
#pragma unroll
    for (int c = 0; c < CC; ++c)
#pragma unroll
        for (int j = 0; j < 2; ++j)
#pragma unroll
            for (int i = 0; i < 4; ++i) corr[c][j][i] = 0.f;

    // ---- class loop ----
#pragma unroll
    for (int c = 0; c < CC; ++c) {
        int bc = b*CC + c;
        __syncthreads();                   // protect As/Bs + cnts reuse
        if (tid < 32) cnts[tid] = 0;
        __syncthreads();

        // A tile: 32 rows x 256 k. Two batches of 4 float4 (MLP), then process.
        const float4* Ag = (const float4*)(attn + ((size_t)bc*QQ + m0)*LL);
        float4*       Og = (float4*)(attn_out + ((size_t)bc*QQ + m0)*LL);
#pragma unroll
        for (int half = 0; half < 2; ++half) {
            float4 v[4];
#pragma unroll
            for (int it = 0; it < 4; ++it)
                v[it] = Ag[(half*4 + it)*256 + tid];
#pragma unroll
            for (int it = 0; it < 4; ++it) {
                int flat = (half*4 + it)*256 + tid;
                int row  = flat >> 6;      // warp-uniform
                int k    = (flat & 63) << 2;
                Og[flat] = v[it];
                int cn = (v[it].x != 0.f) + (v[it].y != 0.f)
                       + (v[it].z != 0.f) + (v[it].w != 0.f);
                cn = __reduce_add_sync(0xFFFFFFFFu, cn);
                if (lane == 0) atomicAdd(&cnts[row], cn);
                __nv_bfloat162 h0 = __floats2bfloat162_rn(v[it].x, v[it].y);
                __nv_bfloat162 h1 = __floats2bfloat162_rn(v[it].z, v[it].w);
                *(uint2*)(As + row*ALD + k) =
                    make_uint2(*(uint32_t*)&h0, *(uint32_t*)&h1);
            }
        }
        // B tile: 64 rows x 256 k bf16 = 2048 uint4; two batches of 4.
        const uint4* Bg = (const uint4*)(g_Ub + (size_t)bc*PSQ*LL);
#pragma unroll
        for (int half = 0; half < 2; ++half) {
            uint4 u[4];
#pragma unroll
            for (int it = 0; it < 4; ++it)
                u[it] = Bg[(half*4 + it)*256 + tid];
#pragma unroll
            for (int it = 0; it < 4; ++it) {
                int flat = (half*4 + it)*256 + tid;
                int row  = flat >> 5;
                int k    = (flat & 31) << 3;
                *(uint4*)(Bs + row*ALD + k) = u[it];
            }
        }
        __syncthreads();
        if (tid < 32) scales[tid] = 1.f / ((float)cnts[tid] + 1e-5f);
        __syncthreads();

        // HMMA: warp computes its 16x16 C tile for class c
        const __nv_bfloat16* Ab = As + (mrow + g)*ALD + tg*2;
#pragma unroll 4
        for (int ks = 0; ks < 16; ++ks) {
            int kk = ks * 16;
            uint32_t a0 = *(const uint32_t*)(Ab + kk);
            uint32_t a1 = *(const uint32_t*)(Ab + 8*ALD + kk);
            uint32_t a2 = *(const uint32_t*)(Ab + kk + 8);
            uint32_t a3 = *(const uint32_t*)(Ab + 8*ALD + kk + 8);
#pragma unroll
            for (int j = 0; j < 2; ++j) {
                const __nv_bfloat16* Bb = Bs + (wc*16 + j*8 + g)*ALD + kk + tg*2;
                uint32_t b0 = *(const uint32_t*)(Bb);
                uint32_t b1 = *(const uint32_t*)(Bb + 8);
                asm volatile(
                    "mma.sync.aligned.m16n8k16.row.col.f32.bf16.bf16.f32 "
                    "{%0,%1,%2,%3}, {%4,%5,%6,%7}, {%8,%9}, {%0,%1,%2,%3};"
                    : "+f"(corr[c][j][0]), "+f"(corr[c][j][1]),
                      "+f"(corr[c][j][2]), "+f"(corr[c][j][3])
                    : "r"(a0), "r"(a1), "r"(a2), "r"(a3), "r"(b0), "r"(b1));
            }
        }
        float s0 = scales[mrow + g];
        float s1 = scales[mrow + g + 8];
#pragma unroll
        for (int j = 0; j < 2; ++j) {
            corr[c][j][0] *= s0; corr[c][j][1] *= s0;
            corr[c][j][2] *= s1; corr[c][j][3] *= s1;
        }
    }

    // ---- fused epilogue: (corr+1)*y, log_softmax, write out ----
#pragma unroll
    for (int r = 0; r < 2; ++r) {
        int qrow = mrow + g + r*8;         // local 0..31
        int q    = m0 + qrow;
        int t0   = ((q & 63) << 3) + tg*2;
        int t1   = t0 + 1;
        float pt0 = (float)(t0 * sc);
        int lt0 = (int)pt0; if (lt0 > 63) lt0 = 63;
        float wt0 = pt0 - (float)lt0;
        int ht0 = lt0 + 1; if (ht0 > 63) ht0 = 63;
        float pt1 = (float)(t1 * sc);
        int lt1 = (int)pt1; if (lt1 > 63) lt1 = 63;
        float wt1 = pt1 - (float)lt1;
        int ht1 = lt1 + 1; if (ht1 > 63) ht1 = 63;

#pragma unroll
        for (int j = 0; j < 2; ++j) {
            int sr = wc*2 + j;
            float v0[CC], v1[CC];
            float m0v = -3.4e38f, m1v = -3.4e38f;
#pragma unroll
            for (int c = 0; c < CC; ++c) {
                const float* yr = yrow + (c*8 + sr)*64;
                float a0 = yr[lt0];
                float y0 = a0 + wt0*(yr[ht0] - a0);
                float a1 = yr[lt1];
                float y1 = a1 + wt1*(yr[ht1] - a1);
                v0[c] = (corr[c][j][r*2+0] + 1.f) * y0;
                v1[c] = (corr[c][j][r*2+1] + 1.f) * y1;
                m0v = fmaxf(m0v, v0[c]);
                m1v = fmaxf(m1v, v1[c]);
            }
            float su0 = 0.f, su1 = 0.f;
#pragma unroll
            for (int c = 0; c < CC; ++c) {
                su0 += __expf(v0[c] - m0v);
                su1 += __expf(v1[c] - m1v);
            }
            float lse0 = logf(su0) + m0v;
            float lse1 = logf(su1) + m1v;
            int s_glob = sh0 + sr;
#pragma unroll
            for (int c = 0; c < CC; ++c) {
                float* op = out + (((size_t)(b*CC + c)) << 18) + (s_glob << 9) + t0;
                *(float2*)op = make_float2(v0[c] - lse0, v1[c] - lse1);
            }
        }
    }
}

// ======================= launch =======================
extern "C" void kernel_launch(void* const* d_in, const int* in_sizes, int n_in,
                              void* d_out, int out_size) {
    const float* x    = (const float*)d_in[0];
    const float* attn = (const float*)d_in[1];
    const float* cw   = (const float*)d_in[2];
    const float* cb   = (const float*)d_in[3];
    float* out = (float*)d_out;

    conv1x1_kernel<<<BB*HS*HS/32, 256>>>(x, cw, cb);
    argmax_pool_kernel<<<(BB*SMDIM*SMDIM + 255)/256, 256>>>();

    static int smem_set = 0;
    if (!smem_set) {
        cudaFuncSetAttribute(fused_kernel,
                             cudaFuncAttributeMaxDynamicSharedMemorySize,
                             FUSED_SMEM);
        smem_set = 1;
    }
    fused_kernel<<<dim3(QQ/32, BB), 256, FUSED_SMEM>>>(attn, out, out + OUT_ELEMS);
}

// round 8
// speedup vs baseline: 3.5360x; 1.0281x over previous
#include <cuda_runtime.h>
#include <cuda_bf16.h>
#include <math.h>
#include <stdint.h>

// Problem constants
#define BB     4
#define CIN    256
#define HS     64
#define SFULL  512
#define CC     8
#define SMDIM  128
#define KP     4
#define PP     8
#define LL     256          // K of matmul
#define QQ     4096         // M total per (b,c)
#define PSQ    64           // N of matmul
#define OUT_ELEMS  (BB*CC*SFULL*SFULL)

// -------- scratch (device globals) --------
__device__ float g_y64[BB*CC*HS*HS];
__device__ __nv_bfloat16 g_Ub[BB*CC*PSQ*LL];            // [bc][p=64][k=256] bf16

__device__ __forceinline__ uint32_t smem_u32(const void* p) {
    uint32_t a;
    asm("{ .reg .u64 t; cvta.to.shared.u64 t, %1; cvt.u32.u64 %0, t; }"
        : "=r"(a) : "l"(p));
    return a;
}
#define CP16(dst_u32, src) \
    asm volatile("cp.async.cg.shared.global [%0], [%1], 16;" \
                 :: "r"(dst_u32), "l"(src))
#define CP_COMMIT() asm volatile("cp.async.commit_group;")
#define CP_WAIT1()  asm volatile("cp.async.wait_group 1;")

// ================= Kernel A: 1x1 conv (256 -> 8), 16px x 16 ic-split =================
__global__ void __launch_bounds__(256)
conv1x1_kernel(const float* __restrict__ x,
               const float* __restrict__ w,
               const float* __restrict__ b) {
    __shared__ float ws[CC*CIN];
    __shared__ float sacc[16*9];
    int tid = threadIdx.x;
    for (int i = tid; i < CC*CIN; i += 256) ws[i] = w[i];
    if (tid < 16*9) sacc[tid] = 0.f;
    __syncthreads();

    int px  = tid & 15;
    int icq = tid >> 4;                    // 0..15, 16 ic each
    int pid = blockIdx.x*16 + px;
    int bb  = pid >> 12;
    int p   = pid & 4095;

    float acc[CC];
#pragma unroll
    for (int c = 0; c < CC; ++c) acc[c] = 0.f;

    const float* xp = x + (size_t)bb*CIN*HS*HS + (size_t)icq*16*HS*HS + p;
#pragma unroll
    for (int ic = 0; ic < 16; ++ic) {
        float xv = xp[(size_t)ic*HS*HS];
        int icg = icq*16 + ic;
#pragma unroll
        for (int c = 0; c < CC; ++c) acc[c] += xv * ws[c*CIN + icg];
    }
#pragma unroll
    for (int c = 0; c < CC; ++c) atomicAdd(&sacc[px*9 + c], acc[c]);
    __syncthreads();

    if (tid < 16) {
        int pid2 = blockIdx.x*16 + tid;
        int bb2  = pid2 >> 12;
        int p2   = pid2 & 4095;
#pragma unroll
        for (int c = 0; c < CC; ++c)
            g_y64[(bb2*CC + c)*HS*HS + p2] = sacc[tid*9 + c] + b[c];
    }
}

// ========= Kernel B: bilinear->argmax->4x4 pool -> unfold (bf16, [p][k]) =========
__global__ void argmax_pool_kernel() {
    int idx = blockIdx.x * blockDim.x + threadIdx.x;
    if (idx >= BB*SMDIM*SMDIM) return;
    int bb = idx >> 14;
    int r  = idx & 16383;
    int u  = r >> 7;
    int v  = r & 127;

    const double sc = 63.0 / 511.0;
    int cnt[CC];
#pragma unroll
    for (int c = 0; c < CC; ++c) cnt[c] = 0;

    const float* yb = g_y64 + bb*CC*HS*HS;

#pragma unroll
    for (int i = 0; i < KP; ++i) {
        int s = u*KP + i;
        float ps = (float)(s * sc);
        int lo_s = (int)ps; if (lo_s > 63) lo_s = 63;
        float wsv = ps - (float)lo_s;
        int hi_s = lo_s + 1; if (hi_s > 63) hi_s = 63;
#pragma unroll
        for (int j = 0; j < KP; ++j) {
            int t = v*KP + j;
            float pt = (float)(t * sc);
            int lo_t = (int)pt; if (lo_t > 63) lo_t = 63;
            float wtv = pt - (float)lo_t;
            int hi_t = lo_t + 1; if (hi_t > 63) hi_t = 63;

            float w00 = (1.f-wsv)*(1.f-wtv);
            float w01 = (1.f-wsv)*wtv;
            float w10 = wsv*(1.f-wtv);
            float w11 = wsv*wtv;

            float best = -3.4e38f;
            int bi = 0;
#pragma unroll
            for (int c = 0; c < CC; ++c) {
                const float* yc = yb + c*HS*HS;
                float yv = w00*yc[lo_s*HS + lo_t] + w01*yc[lo_s*HS + hi_t]
                         + w10*yc[hi_s*HS + lo_t] + w11*yc[hi_s*HS + hi_t];
                if (yv > best) { best = yv; bi = c; }
            }
            cnt[bi]++;
        }
    }

    int p = ((u & 7) << 3) | (v & 7);
    int l = ((u >> 3) << 4) | (v >> 3);
#pragma unroll
    for (int c = 0; c < CC; ++c)
        g_Ub[((bb*CC + c)*PSQ + p)*LL + l] =
            __float2bfloat16((float)cnt[c] * 0.0625f);
}

// ====== Kernel D: fused GEMM(8 classes) + nz + passthrough + softmax, cp.async pipelined ======
#define ALD 264
#define OFF_AS    0
#define OFF_BS    16896                    // 32*ALD*2
#define OFF_STAGE 50688                    // + 64*ALD*2
#define OFF_YROW  83456                    // + 2*16*256*4
#define FUSED_SMEM 99840                   // + 4096*4

__global__ void __launch_bounds__(256, 2)
fused_kernel(const float* __restrict__ attn, float* __restrict__ out,
             float* __restrict__ attn_out) {
    extern __shared__ char dsm[];
    __nv_bfloat16* As = (__nv_bfloat16*)(dsm + OFF_AS);     // [32][ALD]
    __nv_bfloat16* Bs = (__nv_bfloat16*)(dsm + OFF_BS);     // [64][ALD]
    float* stagef     = (float*)(dsm + OFF_STAGE);          // [2][16*256]
    float* yrow       = (float*)(dsm + OFF_YROW);           // [8c][8sr][64]
    __shared__ float scales[CC][32];
    __shared__ int   cnts[CC][32];

    const int tid  = threadIdx.x;
    const int wid  = tid >> 5, lane = tid & 31;
    const int g    = lane >> 2, tg = lane & 3;
    const int wr   = wid & 1,  wc  = wid >> 1;
    const int mrow = wr * 16;
    const int mt   = blockIdx.x;
    const int b    = blockIdx.y;
    const int m0   = mt * 32;
    const int sh0  = (mt >> 1) * 8;
    const double sc = 63.0 / 511.0;

    ((int*)cnts)[tid] = 0;                 // 256 ints exactly

    const uint32_t stage_u32 = smem_u32(stagef);
    const uint32_t bs_u32    = smem_u32(Bs);

    // ---- prologue: prefetch stage0 (A half0 + B class0), stage1 (A half1) ----
    {
        const char* a0 = (const char*)(attn + ((size_t)(b*CC+0)*QQ + m0)*LL);
        const char* bsrc = (const char*)(g_Ub + (size_t)(b*CC+0)*PSQ*LL);
#pragma unroll
        for (int i = 0; i < 4; ++i) {
            int ch = i*256 + tid;
            CP16(stage_u32 + ch*16, a0 + ch*16);
        }
#pragma unroll
        for (int i = 0; i < 8; ++i) {
            int ch = i*256 + tid;
            CP16(bs_u32 + (ch >> 5)*528 + (ch & 31)*16, bsrc + ch*16);
        }
        CP_COMMIT();
#pragma unroll
        for (int i = 0; i < 4; ++i) {
            int ch = i*256 + tid;
            CP16(stage_u32 + 16384 + ch*16, a0 + 16384 + ch*16);
        }
        CP_COMMIT();
    }

    // ---- yrow precompute (overlaps prologue cp.async latency) ----
#pragma unroll
    for (int it = 0; it < 16; ++it) {
        int i   = it*256 + tid;
        int c   = i >> 9;
        int sr  = (i >> 6) & 7;
        int col = i & 63;
        int s   = sh0 + sr;
        float ps = (float)(s * sc);
        int ls = (int)ps; if (ls > 63) ls = 63;
        float wsv = ps - (float)ls;
        int hs = ls + 1; if (hs > 63) hs = 63;
        const float* yc = g_y64 + (b*CC + c)*HS*HS;
        float lo = yc[ls*HS + col], hi = yc[hs*HS + col];
        yrow[i] = lo + wsv*(hi - lo);
    }

    float corr[CC][2][4];
#pragma unroll
    for (int c = 0; c < CC; ++c)
#pragma unroll
        for (int j = 0; j < 2; ++j)
#pragma unroll
            for (int i = 0; i < 4; ++i) corr[c][j][i] = 0.f;

    // ---- pipelined stage loop: 16 stages = 8 classes x 2 half-tiles ----
#pragma unroll
    for (int s = 0; s < 16; ++s) {
        const int c = s >> 1, h = s & 1;
        const int bc = b*CC + c;

        CP_WAIT1();
        __syncthreads();                   // stage s data visible; prev readers done

        // process stage s: passthrough + nz + bf16 convert into As
        float4* Og  = (float4*)(attn_out + ((size_t)bc*QQ + m0)*LL);
        const float4* buf = (const float4*)(stagef + (s & 1)*4096);
#pragma unroll
        for (int i = 0; i < 4; ++i) {
            int flat = i*256 + tid;        // float4 idx within half
            int row  = h*16 + (flat >> 6); // warp-uniform
            int k    = (flat & 63) << 2;
            float4 v = buf[flat];
            Og[h*1024 + flat] = v;
            int cn = (v.x != 0.f) + (v.y != 0.f) + (v.z != 0.f) + (v.w != 0.f);
            cn = __reduce_add_sync(0xFFFFFFFFu, cn);
            if (lane == 0) atomicAdd(&cnts[c][row], cn);
            __nv_bfloat162 h0 = __floats2bfloat162_rn(v.x, v.y);
            __nv_bfloat162 h1 = __floats2bfloat162_rn(v.z, v.w);
            *(uint2*)(As + row*ALD + k) = make_uint2(*(uint32_t*)&h0, *(uint32_t*)&h1);
        }
        __syncthreads();                   // buf[s&1] free; As half done

        if (h == 0) {
            // prefetch stage s+2 = (class c+1, half0)
            if (s + 2 <= 15) {
                int c2 = (s+2) >> 1;
                const char* asrc = (const char*)(attn +
                    ((size_t)(b*CC+c2)*QQ + m0)*LL);
#pragma unroll
                for (int i = 0; i < 4; ++i) {
                    int ch = i*256 + tid;
                    CP16(stage_u32 + (s & 1)*16384 + ch*16, asrc + ch*16);
                }
            }
            CP_COMMIT();
        } else {
            if (tid < 32) scales[c][tid] = 1.f / ((float)cnts[c][tid] + 1e-5f);
            __syncthreads();               // scales + full As visible

            // HMMA for class c
            const __nv_bfloat16* Ab = As + (mrow + g)*ALD + tg*2;
#pragma unroll 4
            for (int ks = 0; ks < 16; ++ks) {
                int kk = ks * 16;
                uint32_t a0 = *(const uint32_t*)(Ab + kk);
                uint32_t a1 = *(const uint32_t*)(Ab + 8*ALD + kk);
                uint32_t a2 = *(const uint32_t*)(Ab + kk + 8);
                uint32_t a3 = *(const uint32_t*)(Ab + 8*ALD + kk + 8);
#pragma unroll
                for (int j = 0; j < 2; ++j) {
                    const __nv_bfloat16* Bb = Bs + (wc*16 + j*8 + g)*ALD + kk + tg*2;
                    uint32_t b0 = *(const uint32_t*)(Bb);
                    uint32_t b1 = *(const uint32_t*)(Bb + 8);
                    asm volatile(
                        "mma.sync.aligned.m16n8k16.row.col.f32.bf16.bf16.f32 "
                        "{%0,%1,%2,%3}, {%4,%5,%6,%7}, {%8,%9}, {%0,%1,%2,%3};"
                        : "+f"(corr[c][j][0]), "+f"(corr[c][j][1]),
                          "+f"(corr[c][j][2]), "+f"(corr[c][j][3])
                        : "r"(a0), "r"(a1), "r"(a2), "r"(a3), "r"(b0), "r"(b1));
                }
            }
            float s0 = scales[c][mrow + g];
            float s1 = scales[c][mrow + g + 8];
#pragma unroll
            for (int j = 0; j < 2; ++j) {
                corr[c][j][0] *= s0; corr[c][j][1] *= s0;
                corr[c][j][2] *= s1; corr[c][j][3] *= s1;
            }
            __syncthreads();               // all MMA reads of As/Bs done

            // prefetch stage s+2 = (class c+1, half1) + B(c+1)
            if (s + 2 <= 15) {
                int c2 = (s+2) >> 1;
                const char* asrc = (const char*)(attn +
                    ((size_t)(b*CC+c2)*QQ + m0 + 16)*LL);   // half1 rows (FIX)
#pragma unroll
                for (int i = 0; i < 4; ++i) {
                    int ch = i*256 + tid;
                    CP16(stage_u32 + (s & 1)*16384 + ch*16, asrc + ch*16);
                }
                const char* bsrc = (const char*)(g_Ub + (size_t)(b*CC+c2)*PSQ*LL);
#pragma unroll
                for (int i = 0; i < 8; ++i) {
                    int ch = i*256 + tid;
                    CP16(bs_u32 + (ch >> 5)*528 + (ch & 31)*16, bsrc + ch*16);
                }
            }
            CP_COMMIT();
        }
    }

    // ---- fused epilogue: (corr+1)*y, log_softmax, write out ----
#pragma unroll
    for (int r = 0; r < 2; ++r) {
        int qrow = mrow + g + r*8;
        int q    = m0 + qrow;
        int t0   = ((q & 63) << 3) + tg*2;
        int t1   = t0 + 1;
        float pt0 = (float)(t0 * sc);
        int lt0 = (int)pt0; if (lt0 > 63) lt0 = 63;
        float wt0 = pt0 - (float)lt0;
        int ht0 = lt0 + 1; if (ht0 > 63) ht0 = 63;
        float pt1 = (float)(t1 * sc);
        int lt1 = (int)pt1; if (lt1 > 63) lt1 = 63;
        float wt1 = pt1 - (float)lt1;
        int ht1 = lt1 + 1; if (ht1 > 63) ht1 = 63;

#pragma unroll
        for (int j = 0; j < 2; ++j) {
            int sr = wc*2 + j;
            float v0[CC], v1[CC];
            float m0v = -3.4e38f, m1v = -3.4e38f;
#pragma unroll
            for (int c = 0; c < CC; ++c) {
                const float* yr = yrow + (c*8 + sr)*64;
                float a0 = yr[lt0];
                float y0 = a0 + wt0*(yr[ht0] - a0);
                float a1 = yr[lt1];
                float y1 = a1 + wt1*(yr[ht1] - a1);
                v0[c] = (corr[c][j][r*2+0] + 1.f) * y0;
                v1[c] = (corr[c][j][r*2+1] + 1.f) * y1;
                m0v = fmaxf(m0v, v0[c]);
                m1v = fmaxf(m1v, v1[c]);
            }
            float su0 = 0.f, su1 = 0.f;
#pragma unroll
            for (int c = 0; c < CC; ++c) {
                su0 += __expf(v0[c] - m0v);
                su1 += __expf(v1[c] - m1v);
            }
            float lse0 = logf(su0) + m0v;
            float lse1 = logf(su1) + m1v;
            int s_glob = sh0 + sr;
#pragma unroll
            for (int c = 0; c < CC; ++c) {
                float* op = out + (((size_t)(b*CC + c)) << 18) + (s_glob << 9) + t0;
                *(float2*)op = make_float2(v0[c] - lse0, v1[c] - lse1);
            }
        }
    }
}

// ======================= launch =======================
extern "C" void kernel_launch(void* const* d_in, const int* in_sizes, int n_in,
                              void* d_out, int out_size) {
    const float* x    = (const float*)d_in[0];
    const float* attn = (const float*)d_in[1];
    const float* cw   = (const float*)d_in[2];
    const float* cb   = (const float*)d_in[3];
    float* out = (float*)d_out;

    conv1x1_kernel<<<BB*HS*HS/16, 256>>>(x, cw, cb);
    argmax_pool_kernel<<<(BB*SMDIM*SMDIM + 255)/256, 256>>>();

    static int smem_set = 0;
    if (!smem_set) {
        cudaFuncSetAttribute(fused_kernel,
                             cudaFuncAttributeMaxDynamicSharedMemorySize,
                             FUSED_SMEM);
        smem_set = 1;
    }
    fused_kernel<<<dim3(QQ/32, BB), 256, FUSED_SMEM>>>(attn, out, out + OUT_ELEMS);
}